// round 9
// baseline (speedup 1.0000x reference)
#include <cuda_runtime.h>
#include <math.h>
#include <stdint.h>

#define TT 512
#define BB 64
#define II 512
#define HH 512
#define NCTA2 128

#define HS_STRIDE 516   // padded h row (floats): 516 % 32 = 4 -> conflict-free b-rows
#define WS_STRIDE 520   // padded W row (floats): 520 % 32 = 8 -> conflict-free jl-rows

// smem layout: [0,64) mbarriers (4 x u64), [64, 64+8320) W slice, then h stage
#define SMEM_WS_OFF 64
#define SMEM_HS_OFF (64 + 4 * WS_STRIDE * 4)
#define SMEM_BYTES  (SMEM_HS_OFF + BB * HS_STRIDE * 4)   // 140480 B

// Global-barrier counter for the persistent phase-2 kernel.
__device__ unsigned int g_bar;

// ---------------------------------------------------------------------------
// Phase 1: C[M=T*B, N=H] = X[M,K] @ W[N,K]^T + (b_ih + b_hh)   (unchanged)
// ---------------------------------------------------------------------------
__global__ __launch_bounds__(256) void gemm_xproj(
    const float* __restrict__ X, const float* __restrict__ W,
    const float* __restrict__ bih, const float* __restrict__ bhh,
    float* __restrict__ C)
{
    __shared__ float As[16][132];
    __shared__ float Bs[16][68];

    const int bm  = blockIdx.x;
    const int bn  = blockIdx.y;
    const int tid = threadIdx.x;
    const int tx  = tid & 15;
    const int ty  = tid >> 4;

    const int arow0 = bm * 128;
    const int brow0 = bn * 64;

    float acc[8][4];
#pragma unroll
    for (int i = 0; i < 8; i++)
#pragma unroll
        for (int j = 0; j < 4; j++) acc[i][j] = 0.0f;

    for (int kt = 0; kt < II; kt += 16) {
#pragma unroll
        for (int i = 0; i < 2; i++) {
            int idx = tid + i * 256;
            int row = idx >> 2;
            int kq  = idx & 3;
            float4 v = *(const float4*)(X + (size_t)(arow0 + row) * II + kt + kq * 4);
            As[kq * 4 + 0][row] = v.x;
            As[kq * 4 + 1][row] = v.y;
            As[kq * 4 + 2][row] = v.z;
            As[kq * 4 + 3][row] = v.w;
        }
        {
            int row = tid >> 2;
            int kq  = tid & 3;
            float4 v = *(const float4*)(W + (size_t)(brow0 + row) * II + kt + kq * 4);
            Bs[kq * 4 + 0][row] = v.x;
            Bs[kq * 4 + 1][row] = v.y;
            Bs[kq * 4 + 2][row] = v.z;
            Bs[kq * 4 + 3][row] = v.w;
        }
        __syncthreads();

#pragma unroll
        for (int k = 0; k < 16; k++) {
            float4 a0 = *(const float4*)&As[k][ty * 8];
            float4 a1 = *(const float4*)&As[k][ty * 8 + 4];
            float4 bv = *(const float4*)&Bs[k][tx * 4];
            float a[8] = {a0.x, a0.y, a0.z, a0.w, a1.x, a1.y, a1.z, a1.w};
            float b4[4] = {bv.x, bv.y, bv.z, bv.w};
#pragma unroll
            for (int i = 0; i < 8; i++)
#pragma unroll
                for (int j = 0; j < 4; j++)
                    acc[i][j] = fmaf(a[i], b4[j], acc[i][j]);
        }
        __syncthreads();
    }

    float4 bias;
    {
        int n = brow0 + tx * 4;
        bias.x = bih[n + 0] + bhh[n + 0];
        bias.y = bih[n + 1] + bhh[n + 1];
        bias.z = bih[n + 2] + bhh[n + 2];
        bias.w = bih[n + 3] + bhh[n + 3];
    }
#pragma unroll
    for (int i = 0; i < 8; i++) {
        int m = arow0 + ty * 8 + i;
        float4 o = make_float4(acc[i][0] + bias.x, acc[i][1] + bias.y,
                               acc[i][2] + bias.z, acc[i][3] + bias.w);
        *(float4*)(C + (size_t)m * HH + brow0 + tx * 4) = o;
    }
}

// ---------------------------------------------------------------------------
// PTX helpers (phase 2)
// ---------------------------------------------------------------------------
__device__ __forceinline__ void mbar_init(uint32_t mbar, uint32_t cnt) {
    asm volatile("mbarrier.init.shared.b64 [%0], %1;" :: "r"(mbar), "r"(cnt) : "memory");
}
__device__ __forceinline__ void mbar_arrive_expect(uint32_t mbar, uint32_t bytes) {
    asm volatile("mbarrier.arrive.expect_tx.shared.b64 _, [%0], %1;"
                 :: "r"(mbar), "r"(bytes) : "memory");
}
__device__ __forceinline__ void mbar_wait(uint32_t mbar, uint32_t parity) {
    asm volatile(
        "{\n\t"
        ".reg .pred P;\n\t"
        "WL_%=:\n\t"
        "mbarrier.try_wait.parity.acquire.cta.shared::cta.b64 P, [%0], %1, 0x989680;\n\t"
        "@P bra WD_%=;\n\t"
        "bra WL_%=;\n\t"
        "WD_%=:\n\t"
        "}" :: "r"(mbar), "r"(parity) : "memory");
}
__device__ __forceinline__ void cp_bulk_row(uint32_t dst, const void* src, uint32_t mbar) {
    asm volatile(
        "cp.async.bulk.shared::cluster.global.mbarrier::complete_tx::bytes [%0], [%1], %2, [%3];"
        :: "r"(dst), "l"(src), "r"(2048u), "r"(mbar) : "memory");
}

// ---------------------------------------------------------------------------
// Phase 2 v2: persistent recurrence. 128 CTAs x 256 threads, CTA owns 4 cols.
// Each step: bulk-copy full hprev (64x512 fp32 = 128KB) global->smem into
// padded rows (4 chunks of 16 rows, one mbarrier each), then every thread
// computes one (b, j) dot product from smem. W slice resident in smem.
// Global sync via monotonic counter barrier. out[] doubles as xproj/output.
// ---------------------------------------------------------------------------
__global__ __launch_bounds__(256, 1) void rnn_steps_v2(
    const float* __restrict__ Whh, float* __restrict__ out,
    unsigned int* __restrict__ bar)
{
    extern __shared__ char smem[];
    const uint32_t sb = (uint32_t)__cvta_generic_to_shared(smem);
    float* ws = (float*)(smem + SMEM_WS_OFF);
    float* hs = (float*)(smem + SMEM_HS_OFF);

    const int cta = blockIdx.x;
    const int tid = threadIdx.x;
    const int b   = tid >> 2;           // 0..63
    const int jl  = tid & 3;            // 0..3
    const int j   = cta * 4 + jl;       // global output column
    const int chunk = b >> 4;           // warp-uniform: which 16-row chunk of h

    // Init 4 chunk mbarriers (arrive count 1: the owner's arrive.expect_tx).
    if (tid < 4) mbar_init(sb + tid * 8, 1u);

    // Load W_hh slice (4 rows x 512) once, padded stride; resident all steps.
    for (int i = tid; i < 4 * (HH / 4); i += 256) {
        int r  = i >> 7;
        int kq = i & 127;
        float4 v = *(const float4*)(Whh + (size_t)(cta * 4 + r) * HH + kq * 4);
        *(float4*)&ws[r * WS_STRIDE + kq * 4] = v;
    }
    __syncthreads();

    // t = 0: h0 = 0 -> h = tanh(xproj)
    float h = tanhf(out[(size_t)b * HH + j]);
    out[(size_t)b * HH + j] = h;
    __threadfence();
    __syncthreads();
    if (tid == 0)
        asm volatile("red.release.gpu.global.add.u32 [%0], 1;" :: "l"(bar) : "memory");

    uint32_t parity = 0;
    const float* hrow = hs + b * HS_STRIDE;
    const float* wrow = ws + jl * WS_STRIDE;

    for (int t = 1; t < TT; t++) {
        // Wait until all CTAs finished step t-1.
        if (tid == 0) {
            unsigned int v;
            const unsigned int target = (unsigned int)t * NCTA2;
            do {
                asm volatile("ld.acquire.gpu.global.u32 %0, [%1];"
                             : "=r"(v) : "l"(bar) : "memory");
            } while (v < target);
        }
        __syncthreads();

        // 4 owner threads each stage one 16-row chunk of hprev into smem.
        // expect_tx precedes the copies in program order of the same thread.
        if (tid < 4) {
            uint32_t mb = sb + tid * 8;
            mbar_arrive_expect(mb, 16u * 2048u);
            const float* src0 = out + (size_t)(t - 1) * BB * HH + (size_t)tid * 16 * HH;
            uint32_t dst0 = sb + SMEM_HS_OFF + (uint32_t)tid * 16 * HS_STRIDE * 4;
#pragma unroll
            for (int r = 0; r < 16; r++)
                cp_bulk_row(dst0 + (uint32_t)r * HS_STRIDE * 4, src0 + (size_t)r * HH, mb);
        }

        // Independent of the copies: this thread's xproj element.
        float xp = out[((size_t)t * BB + b) * HH + j];

        // Wait for this warp's h chunk.
        mbar_wait(sb + chunk * 8, parity);

        // Dot product from smem: h row (b) . W row (jl), 4 split accumulators.
        float a0 = xp, a1 = 0.0f, a2 = 0.0f, a3 = 0.0f;
#pragma unroll 8
        for (int k4 = 0; k4 < HH / 4; k4++) {
            float4 hv = *(const float4*)(hrow + k4 * 4);
            float4 wv = *(const float4*)(wrow + k4 * 4);
            a0 = fmaf(hv.x, wv.x, a0);
            a1 = fmaf(hv.y, wv.y, a1);
            a2 = fmaf(hv.z, wv.z, a2);
            a3 = fmaf(hv.w, wv.w, a3);
        }
        h = tanhf((a0 + a1) + (a2 + a3));
        out[((size_t)t * BB + b) * HH + j] = h;
        parity ^= 1;

        __threadfence();
        __syncthreads();
        if (tid == 0)
            asm volatile("red.release.gpu.global.add.u32 [%0], 1;" :: "l"(bar) : "memory");
    }

    // h_n tail: t = T-1 value still in register.
    out[(size_t)TT * BB * HH + (size_t)b * HH + j] = h;
}

// ---------------------------------------------------------------------------
// Launch
// Inputs: x [T,B,I], w_ih [H,I], w_hh [H,H], b_ih [H], b_hh [H]
// Output: output [T,B,H] ++ h_n [B,H]  (fp32)
// ---------------------------------------------------------------------------
extern "C" void kernel_launch(void* const* d_in, const int* in_sizes, int n_in,
                              void* d_out, int out_size)
{
    (void)in_sizes; (void)n_in; (void)out_size;
    const float* x    = (const float*)d_in[0];
    const float* w_ih = (const float*)d_in[1];
    const float* w_hh = (const float*)d_in[2];
    const float* b_ih = (const float*)d_in[3];
    const float* b_hh = (const float*)d_in[4];
    float* out = (float*)d_out;

    // Allow >48KB dynamic smem (idempotent; not a stream op, capture-safe).
    cudaFuncSetAttribute(rnn_steps_v2, cudaFuncAttributeMaxDynamicSharedMemorySize,
                         SMEM_BYTES);

    // Reset the global barrier counter (graph-capturable memset node).
    void* bar_ptr = nullptr;
    cudaGetSymbolAddress(&bar_ptr, g_bar);
    cudaMemsetAsync(bar_ptr, 0, sizeof(unsigned int));

    // Phase 1: xproj into d_out
    dim3 g1((TT * BB) / 128, HH / 64);
    gemm_xproj<<<g1, 256>>>(x, w_ih, b_ih, b_hh, out);

    // Phase 2: persistent recurrence
    rnn_steps_v2<<<NCTA2, 256, SMEM_BYTES>>>(w_hh, out, (unsigned int*)bar_ptr);
}

// round 10
// speedup vs baseline: 1.3782x; 1.3782x over previous
#include <cuda_runtime.h>
#include <math.h>
#include <stdint.h>

#define TT 512
#define BB 64
#define II 512
#define HH 512

// ---------------------------------------------------------------------------
// Phase 1: C[M=T*B, N=H] = X[M,K] @ W[N,K]^T + (b_ih + b_hh)   (unchanged)
// ---------------------------------------------------------------------------
__global__ __launch_bounds__(256) void gemm_xproj(
    const float* __restrict__ X, const float* __restrict__ W,
    const float* __restrict__ bih, const float* __restrict__ bhh,
    float* __restrict__ C)
{
    __shared__ float As[16][132];
    __shared__ float Bs[16][68];

    const int bm  = blockIdx.x;
    const int bn  = blockIdx.y;
    const int tid = threadIdx.x;
    const int tx  = tid & 15;
    const int ty  = tid >> 4;

    const int arow0 = bm * 128;
    const int brow0 = bn * 64;

    float acc[8][4];
#pragma unroll
    for (int i = 0; i < 8; i++)
#pragma unroll
        for (int j = 0; j < 4; j++) acc[i][j] = 0.0f;

    for (int kt = 0; kt < II; kt += 16) {
#pragma unroll
        for (int i = 0; i < 2; i++) {
            int idx = tid + i * 256;
            int row = idx >> 2;
            int kq  = idx & 3;
            float4 v = *(const float4*)(X + (size_t)(arow0 + row) * II + kt + kq * 4);
            As[kq * 4 + 0][row] = v.x;
            As[kq * 4 + 1][row] = v.y;
            As[kq * 4 + 2][row] = v.z;
            As[kq * 4 + 3][row] = v.w;
        }
        {
            int row = tid >> 2;
            int kq  = tid & 3;
            float4 v = *(const float4*)(W + (size_t)(brow0 + row) * II + kt + kq * 4);
            Bs[kq * 4 + 0][row] = v.x;
            Bs[kq * 4 + 1][row] = v.y;
            Bs[kq * 4 + 2][row] = v.z;
            Bs[kq * 4 + 3][row] = v.w;
        }
        __syncthreads();

#pragma unroll
        for (int k = 0; k < 16; k++) {
            float4 a0 = *(const float4*)&As[k][ty * 8];
            float4 a1 = *(const float4*)&As[k][ty * 8 + 4];
            float4 bv = *(const float4*)&Bs[k][tx * 4];
            float a[8] = {a0.x, a0.y, a0.z, a0.w, a1.x, a1.y, a1.z, a1.w};
            float b4[4] = {bv.x, bv.y, bv.z, bv.w};
#pragma unroll
            for (int i = 0; i < 8; i++)
#pragma unroll
                for (int j = 0; j < 4; j++)
                    acc[i][j] = fmaf(a[i], b4[j], acc[i][j]);
        }
        __syncthreads();
    }

    float4 bias;
    {
        int n = brow0 + tx * 4;
        bias.x = bih[n + 0] + bhh[n + 0];
        bias.y = bih[n + 1] + bhh[n + 1];
        bias.z = bih[n + 2] + bhh[n + 2];
        bias.w = bih[n + 3] + bhh[n + 3];
    }
#pragma unroll
    for (int i = 0; i < 8; i++) {
        int m = arow0 + ty * 8 + i;
        float4 o = make_float4(acc[i][0] + bias.x, acc[i][1] + bias.y,
                               acc[i][2] + bias.z, acc[i][3] + bias.w);
        *(float4*)(C + (size_t)m * HH + brow0 + tx * 4) = o;
    }
}

// ---------------------------------------------------------------------------
// Phase 2 v3: batch-partitioned cluster recurrence.
// 16 clusters x 8 CTAs x 512 threads. Cluster owns 4 batches for all 512
// steps; CTA rank r owns h-columns [64r, 64r+64) with its W_hh slice held in
// REGISTERS (thread (jl,kc): W row 64r+jl, k-chunk [64kc,64kc+64), 16 float4).
// h (4 x 512 fp32) lives double-buffered in every CTA's smem, padded into
// 8 chunks of 68 floats (conflict-free LDS.128). Each step:
//   read h from smem  ->  256 reg-FMA  ->  shfl-reduce over kc (8 lanes)
//   ->  8-lane parallel DSMEM fanout of the new values to all cluster CTAs
//   ->  one cluster.sync.
// No global barrier, no L2 h-traffic, no threadfence.
// ---------------------------------------------------------------------------
#define HROW 544   // 8 chunks * 68 floats (padded)

__global__ void __cluster_dims__(8, 1, 1) __launch_bounds__(512, 1)
rnn_cluster(const float* __restrict__ Whh, float* __restrict__ out)
{
    __shared__ float hs[2][4][HROW];   // [buf][batch][padded h row] = 17408 B

    const int cid = blockIdx.x >> 3;       // cluster id, 0..15
    const int r   = blockIdx.x & 7;        // cluster rank, 0..7
    const int tid = threadIdx.x;
    const int jl  = tid >> 3;              // 0..63 : column within CTA
    const int kc  = tid & 7;               // 0..7  : k-chunk / fanout target
    const int jcol = r * 64 + jl;          // global h column
    const int gb0  = cid * 4;              // first batch of this cluster

    // W_hh row slice -> registers (once, resident for all 512 steps)
    float4 w[16];
    {
        const float4* wp = (const float4*)(Whh + (size_t)jcol * HH + kc * 64);
#pragma unroll
        for (int i = 0; i < 16; i++) w[i] = wp[i];
    }

    const uint32_t hs_base = (uint32_t)__cvta_generic_to_shared(hs);
    const uint32_t my_off  = (uint32_t)(r * 68 + jl) * 4;   // this thread's slot in an h row

    // ---- t = 0 : h0 = 0  ->  h = tanh(xproj) ----
    float a[4];
#pragma unroll
    for (int b = 0; b < 4; b++)
        a[b] = tanhf(out[(size_t)(gb0 + b) * HH + jcol]);   // all 8 kc lanes redundantly

#pragma unroll
    for (int b = 0; b < 4; b++) {
        uint32_t laddr = hs_base + (uint32_t)((0 * 4 + b) * HROW) * 4 + my_off;
        uint32_t raddr;
        asm volatile("mapa.shared::cluster.u32 %0, %1, %2;"
                     : "=r"(raddr) : "r"(laddr), "r"(kc));
        asm volatile("st.shared::cluster.f32 [%0], %1;"
                     :: "r"(raddr), "f"(a[b]) : "memory");
    }
    if (kc == 0) {
#pragma unroll
        for (int b = 0; b < 4; b++)
            out[(size_t)(gb0 + b) * HH + jcol] = a[b];
    }
    asm volatile("barrier.cluster.arrive.aligned;" ::: "memory");
    asm volatile("barrier.cluster.wait.aligned;"   ::: "memory");

    // ---- steps 1 .. T-1 ----
    int buf = 0;
    for (int t = 1; t < TT; t++) {
        // prefetch xproj (consumed ~2000 cyc later; latency fully hidden)
        float xp[4];
#pragma unroll
        for (int b = 0; b < 4; b++)
            xp[b] = out[((size_t)t * BB + gb0 + b) * HH + jcol];

        // partial dot: h[b][64kc .. 64kc+64) . w   (4 independent FMA chains)
        const float* hb = &hs[buf][0][0] + kc * 68;
        float ac0 = 0.f, ac1 = 0.f, ac2 = 0.f, ac3 = 0.f;
#pragma unroll
        for (int i = 0; i < 16; i++) {
            float4 h0 = *(const float4*)(hb + 0 * HROW + i * 4);
            float4 h1 = *(const float4*)(hb + 1 * HROW + i * 4);
            float4 h2 = *(const float4*)(hb + 2 * HROW + i * 4);
            float4 h3 = *(const float4*)(hb + 3 * HROW + i * 4);
            ac0 = fmaf(h0.x, w[i].x, ac0); ac0 = fmaf(h0.y, w[i].y, ac0);
            ac0 = fmaf(h0.z, w[i].z, ac0); ac0 = fmaf(h0.w, w[i].w, ac0);
            ac1 = fmaf(h1.x, w[i].x, ac1); ac1 = fmaf(h1.y, w[i].y, ac1);
            ac1 = fmaf(h1.z, w[i].z, ac1); ac1 = fmaf(h1.w, w[i].w, ac1);
            ac2 = fmaf(h2.x, w[i].x, ac2); ac2 = fmaf(h2.y, w[i].y, ac2);
            ac2 = fmaf(h2.z, w[i].z, ac2); ac2 = fmaf(h2.w, w[i].w, ac2);
            ac3 = fmaf(h3.x, w[i].x, ac3); ac3 = fmaf(h3.y, w[i].y, ac3);
            ac3 = fmaf(h3.z, w[i].z, ac3); ac3 = fmaf(h3.w, w[i].w, ac3);
        }
        a[0] = ac0; a[1] = ac1; a[2] = ac2; a[3] = ac3;

        // reduce across the 8 kc lanes (low 3 lane bits), add xp, tanh
#pragma unroll
        for (int b = 0; b < 4; b++) {
            a[b] += __shfl_xor_sync(0xffffffffu, a[b], 1);
            a[b] += __shfl_xor_sync(0xffffffffu, a[b], 2);
            a[b] += __shfl_xor_sync(0xffffffffu, a[b], 4);
            a[b] = tanhf(a[b] + xp[b]);
        }

        // fanout: lane kc delivers the value to CTA kc's write buffer
        const int wb = buf ^ 1;
#pragma unroll
        for (int b = 0; b < 4; b++) {
            uint32_t laddr = hs_base + (uint32_t)((wb * 4 + b) * HROW) * 4 + my_off;
            uint32_t raddr;
            asm volatile("mapa.shared::cluster.u32 %0, %1, %2;"
                         : "=r"(raddr) : "r"(laddr), "r"(kc));
            asm volatile("st.shared::cluster.f32 [%0], %1;"
                         :: "r"(raddr), "f"(a[b]) : "memory");
        }
        if (kc == 0) {
#pragma unroll
            for (int b = 0; b < 4; b++)
                out[((size_t)t * BB + gb0 + b) * HH + jcol] = a[b];
        }

        asm volatile("barrier.cluster.arrive.aligned;" ::: "memory");
        asm volatile("barrier.cluster.wait.aligned;"   ::: "memory");
        buf = wb;
    }

    // ---- h_n tail: last step's values are still in a[] ----
    if (kc == 0) {
#pragma unroll
        for (int b = 0; b < 4; b++)
            out[(size_t)TT * BB * HH + (size_t)(gb0 + b) * HH + jcol] = a[b];
    }
}

// ---------------------------------------------------------------------------
// Launch
// Inputs: x [T,B,I], w_ih [H,I], w_hh [H,H], b_ih [H], b_hh [H]
// Output: output [T,B,H] ++ h_n [B,H]  (fp32)
// ---------------------------------------------------------------------------
extern "C" void kernel_launch(void* const* d_in, const int* in_sizes, int n_in,
                              void* d_out, int out_size)
{
    (void)in_sizes; (void)n_in; (void)out_size;
    const float* x    = (const float*)d_in[0];
    const float* w_ih = (const float*)d_in[1];
    const float* w_hh = (const float*)d_in[2];
    const float* b_ih = (const float*)d_in[3];
    const float* b_hh = (const float*)d_in[4];
    float* out = (float*)d_out;

    // Phase 1: xproj into d_out
    dim3 g1((TT * BB) / 128, HH / 64);
    gemm_xproj<<<g1, 256>>>(x, w_ih, b_ih, b_hh, out);

    // Phase 2: batch-partitioned cluster recurrence (128 CTAs = 16 clusters of 8)
    rnn_cluster<<<128, 512>>>(w_hh, out);
}

// round 11
// speedup vs baseline: 2.5756x; 1.8688x over previous
#include <cuda_runtime.h>
#include <math.h>
#include <stdint.h>

#define TT 512
#define BB 64
#define II 512
#define HH 512

// ---------------------------------------------------------------------------
// Phase 1: C[M=T*B, N=H] = X[M,K] @ W[N,K]^T + (b_ih + b_hh)   (unchanged)
// ---------------------------------------------------------------------------
__global__ __launch_bounds__(256) void gemm_xproj(
    const float* __restrict__ X, const float* __restrict__ W,
    const float* __restrict__ bih, const float* __restrict__ bhh,
    float* __restrict__ C)
{
    __shared__ float As[16][132];
    __shared__ float Bs[16][68];

    const int bm  = blockIdx.x;
    const int bn  = blockIdx.y;
    const int tid = threadIdx.x;
    const int tx  = tid & 15;
    const int ty  = tid >> 4;

    const int arow0 = bm * 128;
    const int brow0 = bn * 64;

    float acc[8][4];
#pragma unroll
    for (int i = 0; i < 8; i++)
#pragma unroll
        for (int j = 0; j < 4; j++) acc[i][j] = 0.0f;

    for (int kt = 0; kt < II; kt += 16) {
#pragma unroll
        for (int i = 0; i < 2; i++) {
            int idx = tid + i * 256;
            int row = idx >> 2;
            int kq  = idx & 3;
            float4 v = *(const float4*)(X + (size_t)(arow0 + row) * II + kt + kq * 4);
            As[kq * 4 + 0][row] = v.x;
            As[kq * 4 + 1][row] = v.y;
            As[kq * 4 + 2][row] = v.z;
            As[kq * 4 + 3][row] = v.w;
        }
        {
            int row = tid >> 2;
            int kq  = tid & 3;
            float4 v = *(const float4*)(W + (size_t)(brow0 + row) * II + kt + kq * 4);
            Bs[kq * 4 + 0][row] = v.x;
            Bs[kq * 4 + 1][row] = v.y;
            Bs[kq * 4 + 2][row] = v.z;
            Bs[kq * 4 + 3][row] = v.w;
        }
        __syncthreads();

#pragma unroll
        for (int k = 0; k < 16; k++) {
            float4 a0 = *(const float4*)&As[k][ty * 8];
            float4 a1 = *(const float4*)&As[k][ty * 8 + 4];
            float4 bv = *(const float4*)&Bs[k][tx * 4];
            float a[8] = {a0.x, a0.y, a0.z, a0.w, a1.x, a1.y, a1.z, a1.w};
            float b4[4] = {bv.x, bv.y, bv.z, bv.w};
#pragma unroll
            for (int i = 0; i < 8; i++)
#pragma unroll
                for (int j = 0; j < 4; j++)
                    acc[i][j] = fmaf(a[i], b4[j], acc[i][j]);
        }
        __syncthreads();
    }

    float4 bias;
    {
        int n = brow0 + tx * 4;
        bias.x = bih[n + 0] + bhh[n + 0];
        bias.y = bih[n + 1] + bhh[n + 1];
        bias.z = bih[n + 2] + bhh[n + 2];
        bias.w = bih[n + 3] + bhh[n + 3];
    }
#pragma unroll
    for (int i = 0; i < 8; i++) {
        int m = arow0 + ty * 8 + i;
        float4 o = make_float4(acc[i][0] + bias.x, acc[i][1] + bias.y,
                               acc[i][2] + bias.z, acc[i][3] + bias.w);
        *(float4*)(C + (size_t)m * HH + brow0 + tx * 4) = o;
    }
}

// ---------------------------------------------------------------------------
// Phase 2 v4: batch-partitioned cluster recurrence, redundancy-free LDS.
// 16 clusters x 8 CTAs x 512 threads. Cluster owns 4 batches; CTA rank r owns
// columns [64r, 64r+64) with W_hh in registers.
// Thread (jg = tid>>5, kc = tid&31): 4 columns (jg*4..+3) x 16-k chunk
// [16kc, 16kc+16). Every lane reads DISTINCT h data (no crossbar redundancy).
// h stored padded: 32 chunks of 16 floats at stride 20 -> conflict-free.
// Partial dots reduced across the 32 kc lanes by a value-splitting butterfly
// (16 shfl); each thread ends with ONE (col,batch) result -> 1 tanh, 1 xp
// load, 1 global store, 4 hoisted DSMEM fanout stores. One cluster.sync/step.
// ---------------------------------------------------------------------------
#define HCH   20                 // padded chunk stride (floats)
#define HROWF (32 * HCH)         // 640 floats per batch row

__global__ void __cluster_dims__(8, 1, 1) __launch_bounds__(512, 1)
rnn_cluster4(const float* __restrict__ Whh, float* __restrict__ out)
{
    __shared__ float hs[2][4][HROWF];   // [buf][batch][padded row] = 20480 B

    const int cid = blockIdx.x >> 3;    // cluster id 0..15
    const int r   = blockIdx.x & 7;     // rank 0..7
    const int tid = threadIdx.x;
    const int jg  = tid >> 5;           // 0..15 column group (4 cols)
    const int kc  = tid & 31;           // 0..31 k-chunk (= lane id)
    const int gb0 = cid * 4;            // first batch of this cluster

    // W_hh: 4 rows x 16 k -> 16 float4 in registers (resident all steps)
    float4 wq[4][4];
#pragma unroll
    for (int c = 0; c < 4; c++) {
        const float4* wp = (const float4*)(Whh + (size_t)(r * 64 + jg * 4 + c) * HH + kc * 16);
#pragma unroll
        for (int i = 0; i < 4; i++) wq[c][i] = wp[i];
    }

    // Result mapping from the butterfly (derived below):
    //   c = 2*bit4(kc) + bit1(kc),  b = 2*bit3(kc) + bit2(kc)
    const int cres = 2 * ((kc >> 4) & 1) + ((kc >> 1) & 1);
    const int bres = 2 * ((kc >> 3) & 1) + ((kc >> 2) & 1);
    const int jres = r * 64 + jg * 4 + cres;     // global column of my result
    const int gbres = gb0 + bres;                // global batch of my result
    const bool writer = (kc & 1) == 0;           // value duplicated on lane pair

    // Hoisted DSMEM fanout addresses: lane parity picks ranks 0-3 or 4-7.
    const uint32_t hs_base = (uint32_t)__cvta_generic_to_shared(hs);
    const uint32_t res_off = (uint32_t)(bres * HROWF + (jres >> 4) * HCH + (jres & 15)) * 4;
    uint32_t raddr[2][4];
#pragma unroll
    for (int buf = 0; buf < 2; buf++) {
        uint32_t laddr = hs_base + (uint32_t)(buf * 4 * HROWF) * 4 + res_off;
#pragma unroll
        for (int rr = 0; rr < 4; rr++) {
            uint32_t tgt = (uint32_t)((kc & 1) * 4 + rr);
            asm volatile("mapa.shared::cluster.u32 %0, %1, %2;"
                         : "=r"(raddr[buf][rr]) : "r"(laddr), "r"(tgt));
        }
    }

    // ---- t = 0 : h0 = 0 -> h = tanh(xproj) ----
    float h = tanhf(out[(size_t)gbres * HH + jres]);
#pragma unroll
    for (int rr = 0; rr < 4; rr++)
        asm volatile("st.shared::cluster.f32 [%0], %1;"
                     :: "r"(raddr[0][rr]), "f"(h) : "memory");
    if (writer) out[(size_t)gbres * HH + jres] = h;
    asm volatile("barrier.cluster.arrive.aligned;" ::: "memory");
    asm volatile("barrier.cluster.wait.aligned;"   ::: "memory");

    // booleans for the butterfly keep/send selection (lane-constant)
    const bool s16 = (kc & 16) != 0;
    const bool s8  = (kc & 8)  != 0;
    const bool s4  = (kc & 4)  != 0;
    const bool s2  = (kc & 2)  != 0;

    const float* xp_base = out + (size_t)gbres * HH + jres;    // + t*BB*HH per step
    float*       st_base = out + (size_t)gbres * HH + jres;

    int buf = 0;
    for (int t = 1; t < TT; t++) {
        // prefetch xproj for my (c,b) — consumed ~2000 cyc later
        float xp = __ldg(xp_base + (size_t)t * BB * HH);

        // partial dots pd[c][b] over k in [16kc, 16kc+16)
        float pd[4][4];
#pragma unroll
        for (int c = 0; c < 4; c++)
#pragma unroll
            for (int b = 0; b < 4; b++) pd[c][b] = 0.0f;

        const float* hb = &hs[buf][0][0] + kc * HCH;
#pragma unroll
        for (int b = 0; b < 4; b++) {
#pragma unroll
            for (int i = 0; i < 4; i++) {
                float4 hv = *(const float4*)(hb + b * HROWF + i * 4);
#pragma unroll
                for (int c = 0; c < 4; c++) {
                    pd[c][b] = fmaf(hv.x, wq[c][i].x, pd[c][b]);
                    pd[c][b] = fmaf(hv.y, wq[c][i].y, pd[c][b]);
                    pd[c][b] = fmaf(hv.z, wq[c][i].z, pd[c][b]);
                    pd[c][b] = fmaf(hv.w, wq[c][i].w, pd[c][b]);
                }
            }
        }

        // Value-splitting butterfly over the 32 kc lanes.
        // Stage 1 (xor 16): split on c-high. q[c'][b], c = 2*s16 + c'.
        float q[2][4];
#pragma unroll
        for (int c1 = 0; c1 < 2; c1++)
#pragma unroll
            for (int b = 0; b < 4; b++) {
                float send = s16 ? pd[c1][b]     : pd[2 + c1][b];
                float keep = s16 ? pd[2 + c1][b] : pd[c1][b];
                q[c1][b] = keep + __shfl_xor_sync(0xffffffffu, send, 16);
            }
        // Stage 2 (xor 8): split on b-high. r2[c'][b'], b = 2*s8 + b'.
        float r2[2][2];
#pragma unroll
        for (int c1 = 0; c1 < 2; c1++)
#pragma unroll
            for (int b1 = 0; b1 < 2; b1++) {
                float send = s8 ? q[c1][b1]     : q[c1][2 + b1];
                float keep = s8 ? q[c1][2 + b1] : q[c1][b1];
                r2[c1][b1] = keep + __shfl_xor_sync(0xffffffffu, send, 8);
            }
        // Stage 3 (xor 4): split on b-low. r3[c'], b-low = s4.
        float r3[2];
#pragma unroll
        for (int c1 = 0; c1 < 2; c1++) {
            float send = s4 ? r2[c1][0] : r2[c1][1];
            float keep = s4 ? r2[c1][1] : r2[c1][0];
            r3[c1] = keep + __shfl_xor_sync(0xffffffffu, send, 4);
        }
        // Stage 4 (xor 2): split on c-low. c-low = s2.
        {
            float send = s2 ? r3[0] : r3[1];
            float keep = s2 ? r3[1] : r3[0];
            r3[0] = keep + __shfl_xor_sync(0xffffffffu, send, 2);
        }
        // Stage 5 (xor 1): final add, value duplicated on lane pairs.
        float dot = r3[0] + __shfl_xor_sync(0xffffffffu, r3[0], 1);

        h = tanhf(dot + xp);

        // fanout to this lane's 4 ranks, opposite buffer
        const int wb = buf ^ 1;
#pragma unroll
        for (int rr = 0; rr < 4; rr++)
            asm volatile("st.shared::cluster.f32 [%0], %1;"
                         :: "r"(raddr[wb][rr]), "f"(h) : "memory");
        if (writer) st_base[(size_t)t * BB * HH] = h;

        asm volatile("barrier.cluster.arrive.aligned;" ::: "memory");
        asm volatile("barrier.cluster.wait.aligned;"   ::: "memory");
        buf = wb;
    }

    // ---- h_n tail ----
    if (writer)
        out[(size_t)TT * BB * HH + (size_t)gbres * HH + jres] = h;
}

// ---------------------------------------------------------------------------
// Launch
// Inputs: x [T,B,I], w_ih [H,I], w_hh [H,H], b_ih [H], b_hh [H]
// Output: output [T,B,H] ++ h_n [B,H]  (fp32)
// ---------------------------------------------------------------------------
extern "C" void kernel_launch(void* const* d_in, const int* in_sizes, int n_in,
                              void* d_out, int out_size)
{
    (void)in_sizes; (void)n_in; (void)out_size;
    const float* x    = (const float*)d_in[0];
    const float* w_ih = (const float*)d_in[1];
    const float* w_hh = (const float*)d_in[2];
    const float* b_ih = (const float*)d_in[3];
    const float* b_hh = (const float*)d_in[4];
    float* out = (float*)d_out;

    // Phase 1: xproj into d_out
    dim3 g1((TT * BB) / 128, HH / 64);
    gemm_xproj<<<g1, 256>>>(x, w_ih, b_ih, b_hh, out);

    // Phase 2: cluster recurrence (128 CTAs = 16 clusters of 8)
    rnn_cluster4<<<128, 512>>>(w_hh, out);
}

// round 12
// speedup vs baseline: 2.8515x; 1.1071x over previous
#include <cuda_runtime.h>
#include <math.h>
#include <stdint.h>

#define TT 512
#define BB 64
#define II 512
#define HH 512

// ---------------------------------------------------------------------------
// Phase 1: C[M=T*B, N=H] = X[M,K] @ W[N,K]^T + (b_ih + b_hh)   (unchanged)
// ---------------------------------------------------------------------------
__global__ __launch_bounds__(256) void gemm_xproj(
    const float* __restrict__ X, const float* __restrict__ W,
    const float* __restrict__ bih, const float* __restrict__ bhh,
    float* __restrict__ C)
{
    __shared__ float As[16][132];
    __shared__ float Bs[16][68];

    const int bm  = blockIdx.x;
    const int bn  = blockIdx.y;
    const int tid = threadIdx.x;
    const int tx  = tid & 15;
    const int ty  = tid >> 4;

    const int arow0 = bm * 128;
    const int brow0 = bn * 64;

    float acc[8][4];
#pragma unroll
    for (int i = 0; i < 8; i++)
#pragma unroll
        for (int j = 0; j < 4; j++) acc[i][j] = 0.0f;

    for (int kt = 0; kt < II; kt += 16) {
#pragma unroll
        for (int i = 0; i < 2; i++) {
            int idx = tid + i * 256;
            int row = idx >> 2;
            int kq  = idx & 3;
            float4 v = *(const float4*)(X + (size_t)(arow0 + row) * II + kt + kq * 4);
            As[kq * 4 + 0][row] = v.x;
            As[kq * 4 + 1][row] = v.y;
            As[kq * 4 + 2][row] = v.z;
            As[kq * 4 + 3][row] = v.w;
        }
        {
            int row = tid >> 2;
            int kq  = tid & 3;
            float4 v = *(const float4*)(W + (size_t)(brow0 + row) * II + kt + kq * 4);
            Bs[kq * 4 + 0][row] = v.x;
            Bs[kq * 4 + 1][row] = v.y;
            Bs[kq * 4 + 2][row] = v.z;
            Bs[kq * 4 + 3][row] = v.w;
        }
        __syncthreads();

#pragma unroll
        for (int k = 0; k < 16; k++) {
            float4 a0 = *(const float4*)&As[k][ty * 8];
            float4 a1 = *(const float4*)&As[k][ty * 8 + 4];
            float4 bv = *(const float4*)&Bs[k][tx * 4];
            float a[8] = {a0.x, a0.y, a0.z, a0.w, a1.x, a1.y, a1.z, a1.w};
            float b4[4] = {bv.x, bv.y, bv.z, bv.w};
#pragma unroll
            for (int i = 0; i < 8; i++)
#pragma unroll
                for (int j = 0; j < 4; j++)
                    acc[i][j] = fmaf(a[i], b4[j], acc[i][j]);
        }
        __syncthreads();
    }

    float4 bias;
    {
        int n = brow0 + tx * 4;
        bias.x = bih[n + 0] + bhh[n + 0];
        bias.y = bih[n + 1] + bhh[n + 1];
        bias.z = bih[n + 2] + bhh[n + 2];
        bias.w = bih[n + 3] + bhh[n + 3];
    }
#pragma unroll
    for (int i = 0; i < 8; i++) {
        int m = arow0 + ty * 8 + i;
        float4 o = make_float4(acc[i][0] + bias.x, acc[i][1] + bias.y,
                               acc[i][2] + bias.z, acc[i][3] + bias.w);
        *(float4*)(C + (size_t)m * HH + brow0 + tx * 4) = o;
    }
}

// ---------------------------------------------------------------------------
// Phase 2 v5: cluster recurrence with VECTORIZED DSMEM fanout.
// 16 clusters x 8 CTAs x 512 threads; CTA rank r owns columns [64r,64r+64),
// cluster owns 4 batches; W_hh in registers (unchanged from v4).
// h buffer layout per batch: 16 groups x 36 floats (k-group of 32 + 4 pad)
//   -> compute LDS.128 conflict-free AND producer regions ~contiguous.
// Fanout: writers stage 256 results into a 288-float block; 576 hoisted
// st.shared::cluster.v4 stores broadcast it to all 8 CTAs (16B transactions
// instead of 4B: 2048 -> 576 transactions per CTA per step).
// ---------------------------------------------------------------------------
#define GRP      36                  // 32 data + 4 pad floats
#define BROW     (16 * GRP)          // 576 floats per batch row
#define BUFFLT   (4 * BROW)          // 2304 floats per buffer
#define BUFBYTES (BUFFLT * 4)        // 9216 B

__device__ __forceinline__ float tanh_fast(float x) {
    float xc = fminf(fmaxf(x, -15.0f), 15.0f);
    float e  = __expf(2.0f * xc);
    return __fdividef(e - 1.0f, e + 1.0f);
}

__global__ void __cluster_dims__(8, 1, 1) __launch_bounds__(512, 1)
rnn_cluster5(const float* __restrict__ Whh, float* __restrict__ out)
{
    __shared__ __align__(16) float hs[2][BUFFLT];   // 18432 B
    __shared__ __align__(16) float stg[4 * 72];     // staging: [batch][72]

    const int cid = blockIdx.x >> 3;    // cluster id 0..15
    const int r   = blockIdx.x & 7;     // rank 0..7
    const int tid = threadIdx.x;
    const int jg  = tid >> 5;           // 0..15 column group (4 cols)
    const int kc  = tid & 31;           // 0..31 k-chunk (= lane id)
    const int gb0 = cid * 4;            // first batch of this cluster

    // W_hh: 4 rows x 16 k -> registers (resident all steps). Lane kc covers
    // k in [16kc, 16kc+16) — same mapping as the h layout below.
    float4 wq[4][4];
#pragma unroll
    for (int c = 0; c < 4; c++) {
        const float4* wp = (const float4*)(Whh + (size_t)(r * 64 + jg * 4 + c) * HH + kc * 16);
#pragma unroll
        for (int i = 0; i < 4; i++) wq[c][i] = wp[i];
    }

    // Butterfly result mapping (identical to v4):
    const int cres  = 2 * ((kc >> 4) & 1) + ((kc >> 1) & 1);
    const int bres  = 2 * ((kc >> 3) & 1) + ((kc >> 2) & 1);
    const int jlres = jg * 4 + cres;             // local column 0..63
    const int jres  = r * 64 + jlres;            // global column
    const int gbres = gb0 + bres;                // global batch
    const bool writer = (kc & 1) == 0;

    // This thread's staging slot (local swizzle: group = jl>>5, offset jl&31)
    const int stg_slot = bres * 72 + ((jlres >> 5) * 36) + (jlres & 31);

    // ---- hoisted fanout descriptors: s = tid (+512 for tid<64) ----
    // s -> target CTA = s/72, f4i = s%72, b = f4i/18,
    // dst float = b*BROW + r*72 + 4*(f4i%18), src f4 = stg + 4*f4i.
    const uint32_t hs_base = (uint32_t)__cvta_generic_to_shared(hs);
    const int nst = (tid < 64) ? 2 : 1;
    uint32_t rdst[2];     // remote dst (buf0) via mapa
    int      sfl[2];      // source float index in stg
#pragma unroll
    for (int e = 0; e < 2; e++) {
        int s   = tid + e * 512;
        if (s >= 576) s = 575;            // dummy (masked by nst)
        int tgt = s / 72;
        int f4i = s % 72;
        int b   = f4i / 18;
        uint32_t laddr = hs_base + (uint32_t)(b * BROW + r * 72 + 4 * (f4i % 18)) * 4u;
        asm volatile("mapa.shared::cluster.u32 %0, %1, %2;"
                     : "=r"(rdst[e]) : "r"(laddr), "r"((uint32_t)tgt));
        sfl[e] = f4i * 4;
    }

    const float* xp_base = out + (size_t)gbres * HH + jres;
    float*       st_base = out + (size_t)gbres * HH + jres;

    // ---- t = 0 : h0 = 0 -> h = tanh(xproj); fanout into buf 0 ----
    float h = tanh_fast(__ldg(xp_base));
    if (writer) {
        st_base[0] = h;
        stg[stg_slot] = h;
    }
    __syncthreads();
#pragma unroll
    for (int e = 0; e < 2; e++) {
        if (e < nst) {
            uint4 v = *(const uint4*)(stg + sfl[e]);
            asm volatile("st.shared::cluster.v4.b32 [%0], {%1,%2,%3,%4};"
                         :: "r"(rdst[e]), "r"(v.x), "r"(v.y), "r"(v.z), "r"(v.w)
                         : "memory");
        }
    }
    asm volatile("barrier.cluster.arrive.aligned;" ::: "memory");
    asm volatile("barrier.cluster.wait.aligned;"   ::: "memory");

    // lane-constant butterfly selectors
    const bool s16 = (kc & 16) != 0;
    const bool s8  = (kc & 8)  != 0;
    const bool s4  = (kc & 4)  != 0;
    const bool s2  = (kc & 2)  != 0;

    // compute-side h base: group kc>>1, half kc&1
    const float* hrd = &hs[0][0] + (kc >> 1) * GRP + (kc & 1) * 16;

    int buf = 0;
    for (int t = 1; t < TT; t++) {
        float xp = __ldg(xp_base + (size_t)t * BB * HH);

        // partial dots pd[c][b] over k in [16kc, 16kc+16), conflict-free LDS
        float pd[4][4];
#pragma unroll
        for (int c = 0; c < 4; c++)
#pragma unroll
            for (int b = 0; b < 4; b++) pd[c][b] = 0.0f;

        const float* hb = hrd + buf * BUFFLT;
#pragma unroll
        for (int b = 0; b < 4; b++) {
#pragma unroll
            for (int i = 0; i < 4; i++) {
                float4 hv = *(const float4*)(hb + b * BROW + i * 4);
#pragma unroll
                for (int c = 0; c < 4; c++) {
                    pd[c][b] = fmaf(hv.x, wq[c][i].x, pd[c][b]);
                    pd[c][b] = fmaf(hv.y, wq[c][i].y, pd[c][b]);
                    pd[c][b] = fmaf(hv.z, wq[c][i].z, pd[c][b]);
                    pd[c][b] = fmaf(hv.w, wq[c][i].w, pd[c][b]);
                }
            }
        }

        // value-splitting butterfly over the 32 kc lanes (16 shfl)
        float q[2][4];
#pragma unroll
        for (int c1 = 0; c1 < 2; c1++)
#pragma unroll
            for (int b = 0; b < 4; b++) {
                float send = s16 ? pd[c1][b]     : pd[2 + c1][b];
                float keep = s16 ? pd[2 + c1][b] : pd[c1][b];
                q[c1][b] = keep + __shfl_xor_sync(0xffffffffu, send, 16);
            }
        float r2[2][2];
#pragma unroll
        for (int c1 = 0; c1 < 2; c1++)
#pragma unroll
            for (int b1 = 0; b1 < 2; b1++) {
                float send = s8 ? q[c1][b1]     : q[c1][2 + b1];
                float keep = s8 ? q[c1][2 + b1] : q[c1][b1];
                r2[c1][b1] = keep + __shfl_xor_sync(0xffffffffu, send, 8);
            }
        float r3[2];
#pragma unroll
        for (int c1 = 0; c1 < 2; c1++) {
            float send = s4 ? r2[c1][0] : r2[c1][1];
            float keep = s4 ? r2[c1][1] : r2[c1][0];
            r3[c1] = keep + __shfl_xor_sync(0xffffffffu, send, 4);
        }
        {
            float send = s2 ? r3[0] : r3[1];
            float keep = s2 ? r3[1] : r3[0];
            r3[0] = keep + __shfl_xor_sync(0xffffffffu, send, 2);
        }
        float dot = r3[0] + __shfl_xor_sync(0xffffffffu, r3[0], 1);

        h = tanh_fast(dot + xp);

        if (writer) {
            st_base[(size_t)t * BB * HH] = h;   // global output (overlaps)
            stg[stg_slot] = h;                  // staging for fanout
        }
        __syncthreads();

        // vectorized DSMEM broadcast into buffer wb of all 8 CTAs
        const int wb = buf ^ 1;
        const uint32_t boff = (uint32_t)wb * BUFBYTES;
#pragma unroll
        for (int e = 0; e < 2; e++) {
            if (e < nst) {
                uint4 v = *(const uint4*)(stg + sfl[e]);
                asm volatile("st.shared::cluster.v4.b32 [%0], {%1,%2,%3,%4};"
                             :: "r"(rdst[e] + boff), "r"(v.x), "r"(v.y), "r"(v.z), "r"(v.w)
                             : "memory");
            }
        }

        asm volatile("barrier.cluster.arrive.aligned;" ::: "memory");
        asm volatile("barrier.cluster.wait.aligned;"   ::: "memory");
        buf = wb;
    }

    // ---- h_n tail ----
    if (writer)
        out[(size_t)TT * BB * HH + (size_t)gbres * HH + jres] = h;
}

// ---------------------------------------------------------------------------
// Launch
// Inputs: x [T,B,I], w_ih [H,I], w_hh [H,H], b_ih [H], b_hh [H]
// Output: output [T,B,H] ++ h_n [B,H]  (fp32)
// ---------------------------------------------------------------------------
extern "C" void kernel_launch(void* const* d_in, const int* in_sizes, int n_in,
                              void* d_out, int out_size)
{
    (void)in_sizes; (void)n_in; (void)out_size;
    const float* x    = (const float*)d_in[0];
    const float* w_ih = (const float*)d_in[1];
    const float* w_hh = (const float*)d_in[2];
    const float* b_ih = (const float*)d_in[3];
    const float* b_hh = (const float*)d_in[4];
    float* out = (float*)d_out;

    // Phase 1: xproj into d_out
    dim3 g1((TT * BB) / 128, HH / 64);
    gemm_xproj<<<g1, 256>>>(x, w_ih, b_ih, b_hh, out);

    // Phase 2: cluster recurrence (128 CTAs = 16 clusters of 8)
    rnn_cluster5<<<128, 512>>>(w_hh, out);
}